// round 11
// baseline (speedup 1.0000x reference)
#include <cuda_runtime.h>

#define BB 256
#define NN 256
#define KNNK 4
#define NPTS (BB*NN)

// ---------------- device scratch (allocation-free requirement) ----------------
__device__ float g_a[NPTS*192];
__device__ float g_b[NPTS*192];
__device__ float g_c[NPTS*192];
__device__ float g_d[NPTS*192];
__device__ float g_h[NPTS*192];
__device__ float g_pool[BB*768];
__device__ int   g_idx[NPTS*KNNK];

// ---------------- helpers ----------------
typedef unsigned long long ull;

__device__ __forceinline__ float leakyf(float x) { return x >= 0.f ? x : 0.01f * x; }

__device__ __forceinline__ ull pack2(float x) {
    ull r; unsigned u = __float_as_uint(x);
    asm("mov.b64 %0, {%1, %1};" : "=l"(r) : "r"(u));
    return r;
}
__device__ __forceinline__ void fma2(ull& d, ull a, ull b) {
    asm("fma.rn.f32x2 %0, %1, %2, %0;" : "+l"(d) : "l"(a), "l"(b));
}
__device__ __forceinline__ ull add2(ull a, ull b) {
    ull r;
    asm("add.rn.f32x2 %0, %1, %2;" : "=l"(r) : "l"(a), "l"(b));
    return r;
}
__device__ __forceinline__ float2 unpack2(ull v) {
    unsigned lo, hi;
    asm("mov.b64 {%0, %1}, %2;" : "=r"(lo), "=r"(hi) : "l"(v));
    return make_float2(__uint_as_float(lo), __uint_as_float(hi));
}

// ---------------- KNN (unchanged) ----------------
__global__ void knn_kernel(const float* __restrict__ pos, int stride, int* __restrict__ idx) {
    __shared__ float sx[NN], sy[NN], sz[NN];
    int b = blockIdx.x, i = threadIdx.x;
    const float* p = pos + ((size_t)b * NN + i) * stride;
    sx[i] = p[0]; sy[i] = p[1]; sz[i] = p[2];
    __syncthreads();
    float xi = sx[i], yi = sy[i], zi = sz[i];
    float d0 = 1e38f, d1 = 1e38f, d2 = 1e38f, d3 = 1e38f;
    int i0 = 0, i1 = 0, i2 = 0, i3 = 0;
    for (int j = 0; j < NN; j++) {
        if (j == i) continue;
        float dx = __fadd_rn(xi, -sx[j]);
        float dy = __fadd_rn(yi, -sy[j]);
        float dz = __fadd_rn(zi, -sz[j]);
        float d = __fmaf_rn(dz, dz, __fmaf_rn(dy, dy, __fmul_rn(dx, dx)));
        if (d < d3) {
            if (d < d2) {
                d3 = d2; i3 = i2;
                if (d < d1) {
                    d2 = d1; i2 = i1;
                    if (d < d0) { d1 = d0; i1 = i0; d0 = d; i0 = j; }
                    else        { d1 = d;  i1 = j; }
                } else { d2 = d; i2 = j; }
            } else { d3 = d; i3 = j; }
        }
    }
    int base = (b * NN + i) * KNNK;
    idx[base] = i0; idx[base + 1] = i1; idx[base + 2] = i2; idx[base + 3] = i3;
}

// ---------------- vectorized-reduction GEMM core: 4 channels x 4 edges per thread ----------------
// Per-(edge,channel) math identical to R7-R9: p_l = sum over k≡l (mod 8),
// q_j = p_j + p_{j+4}, total = ((q0+q1)+(q2+q3)), sequential tail.
// acc layout: acc[c*2+u], u=0 -> edges (0,1) of the quad, u=1 -> edges (2,3).
template<int K, int L>
__device__ __forceinline__ void sweep44(ull acc[8], const float* __restrict__ w, int H, int cq,
                                        const float* __restrict__ smat) {
    #pragma unroll
    for (int i = 0; i < 8; i++) acc[i] = 0;
    constexpr int KMAIN = K & ~7;
    #pragma unroll 2
    for (int k = L; k < KMAIN; k += 8) {
        float4 wv = __ldg((const float4*)(w + (size_t)k * H) + cq);
        ull w0 = pack2(wv.x), w1p = pack2(wv.y), w2p = pack2(wv.z), w3p = pack2(wv.w);
        ulonglong2 vv = *(const ulonglong2*)(smat + k * 16);
        fma2(acc[0], vv.x, w0);  fma2(acc[1], vv.y, w0);
        fma2(acc[2], vv.x, w1p); fma2(acc[3], vv.y, w1p);
        fma2(acc[4], vv.x, w2p); fma2(acc[5], vv.y, w2p);
        fma2(acc[6], vv.x, w3p); fma2(acc[7], vv.y, w3p);
    }
}
__device__ __forceinline__ void addin8(ull a[8], const ull b[8]) {
    #pragma unroll
    for (int i = 0; i < 8; i++) a[i] = add2(a[i], b[i]);
}
template<int K>
__device__ __forceinline__ void gemm_tree44(ull tot[8], const float* __restrict__ w, int H, int cq,
                                            const float* __restrict__ smat) {
    ull T[8], S[8], acc[8];
    sweep44<K, 0>(tot, w, H, cq, smat);
    sweep44<K, 4>(acc, w, H, cq, smat); addin8(tot, acc);  // q0
    sweep44<K, 1>(T,   w, H, cq, smat);
    sweep44<K, 5>(acc, w, H, cq, smat); addin8(T, acc);    // q1
    addin8(tot, T);                                        // q0+q1
    sweep44<K, 2>(T,   w, H, cq, smat);
    sweep44<K, 6>(acc, w, H, cq, smat); addin8(T, acc);    // q2
    sweep44<K, 3>(S,   w, H, cq, smat);
    sweep44<K, 7>(acc, w, H, cq, smat); addin8(S, acc);    // q3
    addin8(T, S);                                          // q2+q3
    addin8(tot, T);
    constexpr int KMAIN = K & ~7;
    #pragma unroll
    for (int k = KMAIN; k < K; k++) {                      // scalar tail
        float4 wv = __ldg((const float4*)(w + (size_t)k * H) + cq);
        ull w0 = pack2(wv.x), w1p = pack2(wv.y), w2p = pack2(wv.z), w3p = pack2(wv.w);
        ulonglong2 vv = *(const ulonglong2*)(smat + k * 16);
        fma2(tot[0], vv.x, w0);  fma2(tot[1], vv.y, w0);
        fma2(tot[2], vv.x, w1p); fma2(tot[3], vv.y, w1p);
        fma2(tot[4], vv.x, w2p); fma2(tot[5], vv.y, w2p);
        fma2(tot[6], vv.x, w3p); fma2(tot[7], vv.y, w3p);
    }
}

// ---------------- fused EdgeConv: 4 points (16 edges)/block, 256 threads ----------------
// thread = (channel-quad cq, edge-quad eq): channels 4cq..4cq+3 x edges 4eq..4eq+3.
// Edge-quad eq == point eq (edges are ordered p*4+k).
template<int FIN, int H>
__global__ void __launch_bounds__(256, 2)
edgeconv_kernel(const float* __restrict__ feat,
                const int* __restrict__ idx,
                const float* __restrict__ w1, const float* __restrict__ b1,
                const float* __restrict__ w2, const float* __restrict__ b2,
                float* __restrict__ out) {
    constexpr int Cout = 192;
    constexpr int F2 = 2 * FIN;
    __shared__ __align__(16) float sf[F2 * 16];   // [k*16 + e]
    __shared__ __align__(16) float s[252 * 16];   // [j*16 + e]
    __shared__ int nb[16];

    int m0 = blockIdx.x * 4;
    int tid = threadIdx.x;

    if (tid < 16) {
        int p = tid >> 2;
        int m = m0 + p;
        nb[tid] = (m & ~(NN - 1)) + idx[m * KNNK + (tid & 3)];
    }
    __syncthreads();

    // build edge features: e = [xi, rn(xj - xi)]
    #pragma unroll 2
    for (int t = tid; t < F2 * 16; t += 256) {
        int e = t & 15, k = t >> 4;
        int p = e >> 2;
        float v;
        if (k < FIN) {
            v = feat[(size_t)(m0 + p) * FIN + k];
        } else {
            int kk = k - FIN;
            v = __fadd_rn(feat[(size_t)nb[e] * FIN + kk], -feat[(size_t)(m0 + p) * FIN + kk]);
        }
        sf[t] = v;
    }
    __syncthreads();

    int cq = tid >> 2, eq = tid & 3;

    // GEMM 1: s = leaky(e @ w1 + b1)
    if (cq < (H + 3) / 4) {
        ull tot[8];
        gemm_tree44<F2>(tot, w1, H, cq, sf + 4 * eq);
        #pragma unroll
        for (int c = 0; c < 4; c++) {
            int j = 4 * cq + c;
            float bb = b1[j];
            float2 r0 = unpack2(tot[2 * c]);      // edges 4eq, 4eq+1
            float2 r1 = unpack2(tot[2 * c + 1]);  // edges 4eq+2, 4eq+3
            *(float4*)(s + j * 16 + 4 * eq) =
                make_float4(leakyf(__fadd_rn(r0.x, bb)), leakyf(__fadd_rn(r0.y, bb)),
                            leakyf(__fadd_rn(r1.x, bb)), leakyf(__fadd_rn(r1.y, bb)));
        }
    }
    __syncthreads();

    // GEMM 2 + leaky + sum over the 4 edges of point eq
    if (cq < Cout / 4) {
        ull tot[8];
        gemm_tree44<H>(tot, w2, Cout, cq, s + 4 * eq);
        float4 res;
        float* rp = (float*)&res;
        #pragma unroll
        for (int c = 0; c < 4; c++) {
            int o = 4 * cq + c;
            float bb = b2[o];
            float2 x0 = unpack2(tot[2 * c]);
            float2 x1 = unpack2(tot[2 * c + 1]);
            rp[c] = leakyf(x0.x + bb) + leakyf(x0.y + bb) +
                    leakyf(x1.x + bb) + leakyf(x1.y + bb);
        }
        *(float4*)(out + (size_t)(m0 + eq) * Cout + 4 * cq) = res;
    }
}

// ---------------- nn1+nn2 fused: 8 points/block, 128 threads, 4ch x 4pt tiles ----------------
// Per-(point,channel) chain: sequential fma over k (same as R7-R9). pq = point-quad.
__global__ void __launch_bounds__(128, 4)
nn12_kernel(const float* __restrict__ x,
            const float* __restrict__ a, const float* __restrict__ b,
            const float* __restrict__ c, const float* __restrict__ d,
            const float* __restrict__ w1, const float* __restrict__ b1,
            const float* __restrict__ w2, const float* __restrict__ b2,
            float* __restrict__ hout) {
    __shared__ __align__(16) float sin_[772 * 8];  // [ch*8 + p]
    __shared__ __align__(16) float sh1[252 * 8];   // [j*8 + p]
    int m0 = blockIdx.x * 8;
    int tid = threadIdx.x;
    for (int e = tid; e < 772 * 8; e += 128) {
        int ch = e >> 3, p = e & 7;
        size_t mp = (size_t)(m0 + p);
        float val;
        if (ch < 4)        val = x[mp * 4 + ch];
        else if (ch < 196) val = a[mp * 192 + (ch - 4)];
        else if (ch < 388) val = b[mp * 192 + (ch - 196)];
        else if (ch < 580) val = c[mp * 192 + (ch - 388)];
        else               val = d[mp * 192 + (ch - 580)];
        sin_[e] = val;
    }
    __syncthreads();
    int cq = tid >> 1, pq = tid & 1;   // channels 4cq..4cq+3, points 4pq..4pq+3
    if (cq < 63) {
        ull acc[8];
        #pragma unroll
        for (int i = 0; i < 8; i++) acc[i] = 0;
        #pragma unroll 2
        for (int k = 0; k < 772; k++) {
            float4 wv = __ldg((const float4*)(w1 + (size_t)k * 252) + cq);
            ull w0 = pack2(wv.x), w1p = pack2(wv.y), w2p = pack2(wv.z), w3p = pack2(wv.w);
            ulonglong2 vv = *(const ulonglong2*)(sin_ + k * 8 + 4 * pq);
            fma2(acc[0], vv.x, w0);  fma2(acc[1], vv.y, w0);
            fma2(acc[2], vv.x, w1p); fma2(acc[3], vv.y, w1p);
            fma2(acc[4], vv.x, w2p); fma2(acc[5], vv.y, w2p);
            fma2(acc[6], vv.x, w3p); fma2(acc[7], vv.y, w3p);
        }
        #pragma unroll
        for (int cc = 0; cc < 4; cc++) {
            int j = 4 * cq + cc;
            float bb = b1[j];
            float2 r0 = unpack2(acc[2 * cc]);
            float2 r1 = unpack2(acc[2 * cc + 1]);
            *(float4*)(sh1 + j * 8 + 4 * pq) =
                make_float4(leakyf(r0.x + bb), leakyf(r0.y + bb),
                            leakyf(r1.x + bb), leakyf(r1.y + bb));
        }
    }
    __syncthreads();
    if (cq < 48) {
        ull acc[8];
        #pragma unroll
        for (int i = 0; i < 8; i++) acc[i] = 0;
        #pragma unroll 2
        for (int mm = 0; mm < 252; mm++) {
            float4 wv = __ldg((const float4*)(w2 + mm * 192) + cq);
            ull w0 = pack2(wv.x), w1p = pack2(wv.y), w2p = pack2(wv.z), w3p = pack2(wv.w);
            ulonglong2 vv = *(const ulonglong2*)(sh1 + mm * 8 + 4 * pq);
            fma2(acc[0], vv.x, w0);  fma2(acc[1], vv.y, w0);
            fma2(acc[2], vv.x, w1p); fma2(acc[3], vv.y, w1p);
            fma2(acc[4], vv.x, w2p); fma2(acc[5], vv.y, w2p);
            fma2(acc[6], vv.x, w3p); fma2(acc[7], vv.y, w3p);
        }
        // per point t (of quad pq): channels 4cq..4cq+3 -> one float4 store
        float bbs[4];
        #pragma unroll
        for (int cc = 0; cc < 4; cc++) bbs[cc] = b2[4 * cq + cc];
        #pragma unroll
        for (int t = 0; t < 4; t++) {
            int u = t >> 1;           // which ull in the pair group
            float4 res;
            float* rp = (float*)&res;
            #pragma unroll
            for (int cc = 0; cc < 4; cc++) {
                float2 r = unpack2(acc[2 * cc + u]);
                rp[cc] = ((t & 1) ? r.y : r.x) + bbs[cc];
            }
            *(float4*)(hout + (size_t)(m0 + 4 * pq + t) * 192 + 4 * cq) = res;
        }
    }
}

// ---------------- pooling (unchanged) ----------------
__global__ void pool_kernel(const float* __restrict__ h, float* __restrict__ pooled) {
    int b = blockIdx.x, cch = threadIdx.x;
    const float* hp = h + (size_t)b * NN * 192 + cch;
    float mx = -1e38f, mn = 1e38f;
    double sm = 0.0;
    #pragma unroll 4
    for (int n = 0; n < NN; n++) {
        float v = hp[(size_t)n * 192];
        mx = fmaxf(mx, v); mn = fminf(mn, v);
        sm += (double)v;
    }
    float smf = (float)sm;
    float* pb = pooled + b * 768;
    pb[cch]       = leakyf(mx);
    pb[192 + cch] = leakyf(mn);
    pb[384 + cch] = leakyf(smf);
    pb[576 + cch] = leakyf(__fmul_rn(smf, (1.0f / 256.0f)));
}

// ---------------- final head (unchanged) ----------------
__global__ void final_kernel(const float* __restrict__ pooled,
                             const float* __restrict__ w3, const float* __restrict__ b3,
                             const float* __restrict__ w4, const float* __restrict__ b4,
                             float* __restrict__ out) {
    __shared__ float sp[768];
    __shared__ float smid[96];
    int b = blockIdx.x, tid = threadIdx.x;
    for (int e = tid; e < 768; e += blockDim.x) sp[e] = pooled[b * 768 + e];
    __syncthreads();
    if (tid < 96) {
        float acc = 0.f;
        for (int k = 0; k < 768; k++) acc = fmaf(sp[k], w3[k * 96 + tid], acc);
        smid[tid] = leakyf(acc + b3[tid]);
    }
    __syncthreads();
    if (tid == 0) {
        float sacc = 0.f;
        for (int k = 0; k < 96; k++) sacc = fmaf(smid[k], w4[k], sacc);
        out[b] = sacc + b4[0];
    }
}

// ---------------- launch ----------------
extern "C" void kernel_launch(void* const* d_in, const int* in_sizes, int n_in,
                              void* d_out, int out_size) {
    const float* x = (const float*)d_in[0];
    const float* prm[24];
    for (int i = 0; i < 24; i++) prm[i] = (const float*)d_in[i + 1];

    float *ga, *gb, *gc, *gd, *gh, *gp;
    int* gi;
    cudaGetSymbolAddress((void**)&ga, g_a);
    cudaGetSymbolAddress((void**)&gb, g_b);
    cudaGetSymbolAddress((void**)&gc, g_c);
    cudaGetSymbolAddress((void**)&gd, g_d);
    cudaGetSymbolAddress((void**)&gh, g_h);
    cudaGetSymbolAddress((void**)&gp, g_pool);
    cudaGetSymbolAddress((void**)&gi, g_idx);

    knn_kernel<<<BB, NN>>>(x, 4, gi);
    edgeconv_kernel<4, 96><<<NPTS / 4, 256>>>(x, gi, prm[0], prm[1], prm[2], prm[3], ga);

    knn_kernel<<<BB, NN>>>(ga, 192, gi);
    edgeconv_kernel<192, 252><<<NPTS / 4, 256>>>(ga, gi, prm[4], prm[5], prm[6], prm[7], gb);

    knn_kernel<<<BB, NN>>>(gb, 192, gi);
    edgeconv_kernel<192, 252><<<NPTS / 4, 256>>>(gb, gi, prm[8], prm[9], prm[10], prm[11], gc);

    knn_kernel<<<BB, NN>>>(gc, 192, gi);
    edgeconv_kernel<192, 252><<<NPTS / 4, 256>>>(gc, gi, prm[12], prm[13], prm[14], prm[15], gd);

    nn12_kernel<<<NPTS / 8, 128>>>(x, ga, gb, gc, gd,
                                   prm[16], prm[17], prm[18], prm[19], gh);

    pool_kernel<<<BB, 192>>>(gh, gp);
    final_kernel<<<BB, 128>>>(gp, prm[20], prm[21], prm[22], prm[23], (float*)d_out);
}

// round 12
// speedup vs baseline: 1.2751x; 1.2751x over previous
#include <cuda_runtime.h>

#define BB 256
#define NN 256
#define KNNK 4
#define NPTS (BB*NN)

// ---------------- device scratch (allocation-free requirement) ----------------
__device__ float g_a[NPTS*192];
__device__ float g_b[NPTS*192];
__device__ float g_c[NPTS*192];
__device__ float g_d[NPTS*192];
__device__ float g_h[NPTS*192];
__device__ float g_pool[BB*768];
__device__ int   g_idx[NPTS*KNNK];

// ---------------- helpers ----------------
typedef unsigned long long ull;

__device__ __forceinline__ float leakyf(float x) { return x >= 0.f ? x : 0.01f * x; }

__device__ __forceinline__ ull pack2(float x) {
    ull r; unsigned u = __float_as_uint(x);
    asm("mov.b64 %0, {%1, %1};" : "=l"(r) : "r"(u));
    return r;
}
__device__ __forceinline__ void fma2(ull& d, ull a, ull b) {
    asm("fma.rn.f32x2 %0, %1, %2, %0;" : "+l"(d) : "l"(a), "l"(b));
}
__device__ __forceinline__ ull add2(ull a, ull b) {
    ull r;
    asm("add.rn.f32x2 %0, %1, %2;" : "=l"(r) : "l"(a), "l"(b));
    return r;
}
__device__ __forceinline__ float2 unpack2(ull v) {
    unsigned lo, hi;
    asm("mov.b64 {%0, %1}, %2;" : "=r"(lo), "=r"(hi) : "l"(v));
    return make_float2(__uint_as_float(lo), __uint_as_float(hi));
}

// ---------------- KNN (unchanged) ----------------
__global__ void knn_kernel(const float* __restrict__ pos, int stride, int* __restrict__ idx) {
    __shared__ float sx[NN], sy[NN], sz[NN];
    int b = blockIdx.x, i = threadIdx.x;
    const float* p = pos + ((size_t)b * NN + i) * stride;
    sx[i] = p[0]; sy[i] = p[1]; sz[i] = p[2];
    __syncthreads();
    float xi = sx[i], yi = sy[i], zi = sz[i];
    float d0 = 1e38f, d1 = 1e38f, d2 = 1e38f, d3 = 1e38f;
    int i0 = 0, i1 = 0, i2 = 0, i3 = 0;
    for (int j = 0; j < NN; j++) {
        if (j == i) continue;
        float dx = __fadd_rn(xi, -sx[j]);
        float dy = __fadd_rn(yi, -sy[j]);
        float dz = __fadd_rn(zi, -sz[j]);
        float d = __fmaf_rn(dz, dz, __fmaf_rn(dy, dy, __fmul_rn(dx, dx)));
        if (d < d3) {
            if (d < d2) {
                d3 = d2; i3 = i2;
                if (d < d1) {
                    d2 = d1; i2 = i1;
                    if (d < d0) { d1 = d0; i1 = i0; d0 = d; i0 = j; }
                    else        { d1 = d;  i1 = j; }
                } else { d2 = d; i2 = j; }
            } else { d3 = d; i3 = j; }
        }
    }
    int base = (b * NN + i) * KNNK;
    idx[base] = i0; idx[base + 1] = i1; idx[base + 2] = i2; idx[base + 3] = i3;
}

// ---------------- class-pair pass: accumulate p_L and p_{L+4} over all 16 edges ----------------
// p_l = sum over k ≡ l (mod 8), ascending k — identical per-lane order to R7-R9.
template<int K, int L>
__device__ __forceinline__ void pass2(ull pA[8], ull pB[8],
                                      const float* __restrict__ wj, int Hs,
                                      const float* __restrict__ smat) {
    #pragma unroll
    for (int i = 0; i < 8; i++) { pA[i] = 0; pB[i] = 0; }
    constexpr int KMAIN = K & ~7;
    #pragma unroll 2
    for (int kc = 0; kc < KMAIN; kc += 8) {
        float wa = __ldg(wj + (size_t)(kc + L) * Hs);
        float wb = __ldg(wj + (size_t)(kc + L + 4) * Hs);
        ull wpa = pack2(wa), wpb = pack2(wb);
        const ulonglong2* sa = (const ulonglong2*)(smat + (kc + L) * 16);
        ulonglong2 a0 = sa[0], a1 = sa[1], a2 = sa[2], a3 = sa[3];
        fma2(pA[0], a0.x, wpa); fma2(pA[1], a0.y, wpa);
        fma2(pA[2], a1.x, wpa); fma2(pA[3], a1.y, wpa);
        fma2(pA[4], a2.x, wpa); fma2(pA[5], a2.y, wpa);
        fma2(pA[6], a3.x, wpa); fma2(pA[7], a3.y, wpa);
        const ulonglong2* sb = (const ulonglong2*)(smat + (kc + L + 4) * 16);
        ulonglong2 b0 = sb[0], b1 = sb[1], b2 = sb[2], b3 = sb[3];
        fma2(pB[0], b0.x, wpb); fma2(pB[1], b0.y, wpb);
        fma2(pB[2], b1.x, wpb); fma2(pB[3], b1.y, wpb);
        fma2(pB[4], b2.x, wpb); fma2(pB[5], b2.y, wpb);
        fma2(pB[6], b3.x, wpb); fma2(pB[7], b3.y, wpb);
    }
}

// full 16-edge GEMM column: tree ((q0+q1)+(q2+q3)) with q_j = p_j + p_{j+4}, then tail.
template<int K>
__device__ __forceinline__ void gemm_col16(ull tot[8],
                                           const float* __restrict__ wj, int Hs,
                                           const float* __restrict__ smat) {
    ull c01[8], q[8], pA[8], pB[8];
    pass2<K, 0>(pA, pB, wj, Hs, smat);           // p0, p4
    #pragma unroll
    for (int i = 0; i < 8; i++) c01[i] = add2(pA[i], pB[i]);      // q0
    pass2<K, 1>(pA, pB, wj, Hs, smat);           // p1, p5
    #pragma unroll
    for (int i = 0; i < 8; i++) q[i] = add2(pA[i], pB[i]);        // q1
    #pragma unroll
    for (int i = 0; i < 8; i++) c01[i] = add2(c01[i], q[i]);      // q0+q1
    pass2<K, 2>(pA, pB, wj, Hs, smat);           // p2, p6
    #pragma unroll
    for (int i = 0; i < 8; i++) q[i] = add2(pA[i], pB[i]);        // q2
    pass2<K, 3>(pA, pB, wj, Hs, smat);           // p3, p7
    #pragma unroll
    for (int i = 0; i < 8; i++) pA[i] = add2(pA[i], pB[i]);       // q3
    #pragma unroll
    for (int i = 0; i < 8; i++) q[i] = add2(q[i], pA[i]);         // q2+q3
    #pragma unroll
    for (int i = 0; i < 8; i++) tot[i] = add2(c01[i], q[i]);      // total
    constexpr int KMAIN = K & ~7;
    #pragma unroll
    for (int k = KMAIN; k < K; k++) {            // sequential scalar tail
        ull wp = pack2(__ldg(wj + (size_t)k * Hs));
        const ulonglong2* sp = (const ulonglong2*)(smat + k * 16);
        ulonglong2 v0 = sp[0], v1 = sp[1], v2 = sp[2], v3 = sp[3];
        fma2(tot[0], v0.x, wp); fma2(tot[1], v0.y, wp);
        fma2(tot[2], v1.x, wp); fma2(tot[3], v1.y, wp);
        fma2(tot[4], v2.x, wp); fma2(tot[5], v2.y, wp);
        fma2(tot[6], v3.x, wp); fma2(tot[7], v3.y, wp);
    }
}

// ---------------- fused EdgeConv: 4 points (16 edges)/block, 256 threads ----------------
// thread = channel j, owning ALL 16 edges (per-lane math unchanged vs R9).
template<int FIN, int H>
__global__ void __launch_bounds__(256, 2)
edgeconv_kernel(const float* __restrict__ feat,
                const int* __restrict__ idx,
                const float* __restrict__ w1, const float* __restrict__ b1,
                const float* __restrict__ w2, const float* __restrict__ b2,
                float* __restrict__ out) {
    constexpr int Cout = 192;
    constexpr int F2 = 2 * FIN;
    __shared__ __align__(16) float sf[F2 * 16];   // [k*16 + e]
    __shared__ __align__(16) float s[252 * 16];   // [j*16 + e]
    __shared__ int nb[16];

    int m0 = blockIdx.x * 4;
    int tid = threadIdx.x;

    if (tid < 16) {
        int p = tid >> 2;
        int m = m0 + p;
        nb[tid] = (m & ~(NN - 1)) + idx[m * KNNK + (tid & 3)];
    }
    __syncthreads();

    // build edge features: e = [xi, rn(xj - xi)]
    #pragma unroll 2
    for (int t = tid; t < F2 * 16; t += 256) {
        int e = t & 15, k = t >> 4;
        int p = e >> 2;
        float v;
        if (k < FIN) {
            v = feat[(size_t)(m0 + p) * FIN + k];
        } else {
            int kk = k - FIN;
            v = __fadd_rn(feat[(size_t)nb[e] * FIN + kk], -feat[(size_t)(m0 + p) * FIN + kk]);
        }
        sf[t] = v;
    }
    __syncthreads();

    // GEMM 1: s = leaky(e @ w1 + b1); one thread per hidden channel j
    if (tid < H) {
        int j = tid;
        ull tot[8];
        gemm_col16<F2>(tot, w1 + j, H, sf);
        float bb = b1[j];
        #pragma unroll
        for (int u = 0; u < 4; u++) {
            float2 r0 = unpack2(tot[2 * u]);
            float2 r1 = unpack2(tot[2 * u + 1]);
            *(float4*)(s + j * 16 + 4 * u) =
                make_float4(leakyf(__fadd_rn(r0.x, bb)), leakyf(__fadd_rn(r0.y, bb)),
                            leakyf(__fadd_rn(r1.x, bb)), leakyf(__fadd_rn(r1.y, bb)));
        }
    }
    __syncthreads();

    // GEMM 2 + leaky + sum over the 4 edges of each point; one thread per output o
    if (tid < Cout) {
        int o = tid;
        ull tot[8];
        gemm_col16<H>(tot, w2 + o, Cout, s);
        float bb = b2[o];
        #pragma unroll
        for (int p = 0; p < 4; p++) {
            float2 x0 = unpack2(tot[2 * p]);      // edges 4p, 4p+1
            float2 x1 = unpack2(tot[2 * p + 1]);  // edges 4p+2, 4p+3
            float r = leakyf(x0.x + bb) + leakyf(x0.y + bb) +
                      leakyf(x1.x + bb) + leakyf(x1.y + bb);
            out[(size_t)(m0 + p) * Cout + o] = r;
        }
    }
}

// ---------------- nn1+nn2 fused per point (R9 verbatim) ----------------
__global__ void nn12_kernel(const float* __restrict__ x,
                            const float* __restrict__ a, const float* __restrict__ b,
                            const float* __restrict__ c, const float* __restrict__ d,
                            const float* __restrict__ w1, const float* __restrict__ b1,
                            const float* __restrict__ w2, const float* __restrict__ b2,
                            float* __restrict__ hout) {
    __shared__ __align__(16) float sin_[772 * 8];
    __shared__ __align__(16) float sh1[252 * 8];
    int m0 = blockIdx.x * 8;
    int tid = threadIdx.x;
    for (int e = tid; e < 772 * 8; e += blockDim.x) {
        int ch = e >> 3, p = e & 7;
        size_t mp = (size_t)(m0 + p);
        float val;
        if (ch < 4)        val = x[mp * 4 + ch];
        else if (ch < 196) val = a[mp * 192 + (ch - 4)];
        else if (ch < 388) val = b[mp * 192 + (ch - 196)];
        else if (ch < 580) val = c[mp * 192 + (ch - 388)];
        else               val = d[mp * 192 + (ch - 580)];
        sin_[e] = val;
    }
    __syncthreads();
    if (tid < 252) {
        int j = tid;
        ull acc[4] = {0, 0, 0, 0};
        #pragma unroll 4
        for (int k = 0; k < 772; k++) {
            ull wp = pack2(__ldg(w1 + (size_t)k * 252 + j));
            const ulonglong2* sp = (const ulonglong2*)&sin_[k * 8];
            ulonglong2 s0 = sp[0], s1 = sp[1];
            fma2(acc[0], s0.x, wp); fma2(acc[1], s0.y, wp);
            fma2(acc[2], s1.x, wp); fma2(acc[3], s1.y, wp);
        }
        float bb = b1[j];
        #pragma unroll
        for (int q = 0; q < 4; q++) {
            float2 r2 = unpack2(acc[q]);
            sh1[j * 8 + q * 2]     = leakyf(r2.x + bb);
            sh1[j * 8 + q * 2 + 1] = leakyf(r2.y + bb);
        }
    }
    __syncthreads();
    if (tid < 192) {
        int o = tid;
        ull acc[4] = {0, 0, 0, 0};
        #pragma unroll 4
        for (int mm = 0; mm < 252; mm++) {
            ull wp = pack2(__ldg(w2 + mm * 192 + o));
            const ulonglong2* sp = (const ulonglong2*)&sh1[mm * 8];
            ulonglong2 s0 = sp[0], s1 = sp[1];
            fma2(acc[0], s0.x, wp); fma2(acc[1], s0.y, wp);
            fma2(acc[2], s1.x, wp); fma2(acc[3], s1.y, wp);
        }
        float bb = b2[o];
        #pragma unroll
        for (int q = 0; q < 4; q++) {
            float2 r2 = unpack2(acc[q]);
            hout[(size_t)(m0 + q * 2) * 192 + o]     = r2.x + bb;
            hout[(size_t)(m0 + q * 2 + 1) * 192 + o] = r2.y + bb;
        }
    }
}

// ---------------- pooling (unchanged) ----------------
__global__ void pool_kernel(const float* __restrict__ h, float* __restrict__ pooled) {
    int b = blockIdx.x, cch = threadIdx.x;
    const float* hp = h + (size_t)b * NN * 192 + cch;
    float mx = -1e38f, mn = 1e38f;
    double sm = 0.0;
    #pragma unroll 4
    for (int n = 0; n < NN; n++) {
        float v = hp[(size_t)n * 192];
        mx = fmaxf(mx, v); mn = fminf(mn, v);
        sm += (double)v;
    }
    float smf = (float)sm;
    float* pb = pooled + b * 768;
    pb[cch]       = leakyf(mx);
    pb[192 + cch] = leakyf(mn);
    pb[384 + cch] = leakyf(smf);
    pb[576 + cch] = leakyf(__fmul_rn(smf, (1.0f / 256.0f)));
}

// ---------------- final head (unchanged) ----------------
__global__ void final_kernel(const float* __restrict__ pooled,
                             const float* __restrict__ w3, const float* __restrict__ b3,
                             const float* __restrict__ w4, const float* __restrict__ b4,
                             float* __restrict__ out) {
    __shared__ float sp[768];
    __shared__ float smid[96];
    int b = blockIdx.x, tid = threadIdx.x;
    for (int e = tid; e < 768; e += blockDim.x) sp[e] = pooled[b * 768 + e];
    __syncthreads();
    if (tid < 96) {
        float acc = 0.f;
        for (int k = 0; k < 768; k++) acc = fmaf(sp[k], w3[k * 96 + tid], acc);
        smid[tid] = leakyf(acc + b3[tid]);
    }
    __syncthreads();
    if (tid == 0) {
        float sacc = 0.f;
        for (int k = 0; k < 96; k++) sacc = fmaf(smid[k], w4[k], sacc);
        out[b] = sacc + b4[0];
    }
}

// ---------------- launch ----------------
extern "C" void kernel_launch(void* const* d_in, const int* in_sizes, int n_in,
                              void* d_out, int out_size) {
    const float* x = (const float*)d_in[0];
    const float* prm[24];
    for (int i = 0; i < 24; i++) prm[i] = (const float*)d_in[i + 1];

    float *ga, *gb, *gc, *gd, *gh, *gp;
    int* gi;
    cudaGetSymbolAddress((void**)&ga, g_a);
    cudaGetSymbolAddress((void**)&gb, g_b);
    cudaGetSymbolAddress((void**)&gc, g_c);
    cudaGetSymbolAddress((void**)&gd, g_d);
    cudaGetSymbolAddress((void**)&gh, g_h);
    cudaGetSymbolAddress((void**)&gp, g_pool);
    cudaGetSymbolAddress((void**)&gi, g_idx);

    knn_kernel<<<BB, NN>>>(x, 4, gi);
    edgeconv_kernel<4, 96><<<NPTS / 4, 256>>>(x, gi, prm[0], prm[1], prm[2], prm[3], ga);

    knn_kernel<<<BB, NN>>>(ga, 192, gi);
    edgeconv_kernel<192, 252><<<NPTS / 4, 256>>>(ga, gi, prm[4], prm[5], prm[6], prm[7], gb);

    knn_kernel<<<BB, NN>>>(gb, 192, gi);
    edgeconv_kernel<192, 252><<<NPTS / 4, 256>>>(gb, gi, prm[8], prm[9], prm[10], prm[11], gc);

    knn_kernel<<<BB, NN>>>(gc, 192, gi);
    edgeconv_kernel<192, 252><<<NPTS / 4, 256>>>(gc, gi, prm[12], prm[13], prm[14], prm[15], gd);

    nn12_kernel<<<NPTS / 8, 256>>>(x, ga, gb, gc, gd,
                                   prm[16], prm[17], prm[18], prm[19], gh);

    pool_kernel<<<BB, 192>>>(gh, gp);
    final_kernel<<<BB, 128>>>(gp, prm[20], prm[21], prm[22], prm[23], (float*)d_out);
}

// round 13
// speedup vs baseline: 1.4674x; 1.1508x over previous
#include <cuda_runtime.h>

#define BB 256
#define NN 256
#define KNNK 4
#define NPTS (BB*NN)

// ---------------- device scratch ----------------
__device__ float g_a[NPTS*192];
__device__ float g_b[NPTS*192];
__device__ float g_c[NPTS*192];
__device__ float g_d[NPTS*192];
__device__ float g_h[NPTS*192];
__device__ float g_pool[BB*768];
__device__ int   g_idx[NPTS*KNNK];

// ---------------- helpers ----------------
typedef unsigned long long ull;

__device__ __forceinline__ float leakyf(float x) { return x >= 0.f ? x : 0.01f * x; }

__device__ __forceinline__ ull pack2(float x) {
    ull r; unsigned u = __float_as_uint(x);
    asm("mov.b64 %0, {%1, %1};" : "=l"(r) : "r"(u));
    return r;
}
__device__ __forceinline__ void fma2(ull& d, ull a, ull b) {
    asm("fma.rn.f32x2 %0, %1, %2, %0;" : "+l"(d) : "l"(a), "l"(b));
}
__device__ __forceinline__ ull add2(ull a, ull b) {
    ull r;
    asm("add.rn.f32x2 %0, %1, %2;" : "=l"(r) : "l"(a), "l"(b));
    return r;
}
__device__ __forceinline__ float2 unpack2(ull v) {
    unsigned lo, hi;
    asm("mov.b64 {%0, %1}, %2;" : "=r"(lo), "=r"(hi) : "l"(v));
    return make_float2(__uint_as_float(lo), __uint_as_float(hi));
}

// ---------------- KNN (unchanged) ----------------
__global__ void knn_kernel(const float* __restrict__ pos, int stride, int* __restrict__ idx) {
    __shared__ float sx[NN], sy[NN], sz[NN];
    int b = blockIdx.x, i = threadIdx.x;
    const float* p = pos + ((size_t)b * NN + i) * stride;
    sx[i] = p[0]; sy[i] = p[1]; sz[i] = p[2];
    __syncthreads();
    float xi = sx[i], yi = sy[i], zi = sz[i];
    float d0 = 1e38f, d1 = 1e38f, d2 = 1e38f, d3 = 1e38f;
    int i0 = 0, i1 = 0, i2 = 0, i3 = 0;
    for (int j = 0; j < NN; j++) {
        if (j == i) continue;
        float dx = __fadd_rn(xi, -sx[j]);
        float dy = __fadd_rn(yi, -sy[j]);
        float dz = __fadd_rn(zi, -sz[j]);
        float d = __fmaf_rn(dz, dz, __fmaf_rn(dy, dy, __fmul_rn(dx, dx)));
        if (d < d3) {
            if (d < d2) {
                d3 = d2; i3 = i2;
                if (d < d1) {
                    d2 = d1; i2 = i1;
                    if (d < d0) { d1 = d0; i1 = i0; d0 = d; i0 = j; }
                    else        { d1 = d;  i1 = j; }
                } else { d2 = d; i2 = j; }
            } else { d3 = d; i3 = j; }
        }
    }
    int base = (b * NN + i) * KNNK;
    idx[base] = i0; idx[base + 1] = i1; idx[base + 2] = i2; idx[base + 3] = i3;
}

// ================= generic class-pair GEMM (R12 verbatim) =================
template<int K, int L>
__device__ __forceinline__ void pass2(ull pA[8], ull pB[8],
                                      const float* __restrict__ wj, int Hs,
                                      const float* __restrict__ smat) {
    #pragma unroll
    for (int i = 0; i < 8; i++) { pA[i] = 0; pB[i] = 0; }
    constexpr int KMAIN = K & ~7;
    #pragma unroll 2
    for (int kc = 0; kc < KMAIN; kc += 8) {
        float wa = __ldg(wj + (size_t)(kc + L) * Hs);
        float wb = __ldg(wj + (size_t)(kc + L + 4) * Hs);
        ull wpa = pack2(wa), wpb = pack2(wb);
        const ulonglong2* sa = (const ulonglong2*)(smat + (kc + L) * 16);
        ulonglong2 a0 = sa[0], a1 = sa[1], a2 = sa[2], a3 = sa[3];
        fma2(pA[0], a0.x, wpa); fma2(pA[1], a0.y, wpa);
        fma2(pA[2], a1.x, wpa); fma2(pA[3], a1.y, wpa);
        fma2(pA[4], a2.x, wpa); fma2(pA[5], a2.y, wpa);
        fma2(pA[6], a3.x, wpa); fma2(pA[7], a3.y, wpa);
        const ulonglong2* sb = (const ulonglong2*)(smat + (kc + L + 4) * 16);
        ulonglong2 b0 = sb[0], b1 = sb[1], b2 = sb[2], b3 = sb[3];
        fma2(pB[0], b0.x, wpb); fma2(pB[1], b0.y, wpb);
        fma2(pB[2], b1.x, wpb); fma2(pB[3], b1.y, wpb);
        fma2(pB[4], b2.x, wpb); fma2(pB[5], b2.y, wpb);
        fma2(pB[6], b3.x, wpb); fma2(pB[7], b3.y, wpb);
    }
}
template<int K>
__device__ __forceinline__ void gemm_col16(ull tot[8],
                                           const float* __restrict__ wj, int Hs,
                                           const float* __restrict__ smat) {
    ull c01[8], q[8], pA[8], pB[8];
    pass2<K, 0>(pA, pB, wj, Hs, smat);
    #pragma unroll
    for (int i = 0; i < 8; i++) c01[i] = add2(pA[i], pB[i]);
    pass2<K, 1>(pA, pB, wj, Hs, smat);
    #pragma unroll
    for (int i = 0; i < 8; i++) q[i] = add2(pA[i], pB[i]);
    #pragma unroll
    for (int i = 0; i < 8; i++) c01[i] = add2(c01[i], q[i]);
    pass2<K, 2>(pA, pB, wj, Hs, smat);
    #pragma unroll
    for (int i = 0; i < 8; i++) q[i] = add2(pA[i], pB[i]);
    pass2<K, 3>(pA, pB, wj, Hs, smat);
    #pragma unroll
    for (int i = 0; i < 8; i++) pA[i] = add2(pA[i], pB[i]);
    #pragma unroll
    for (int i = 0; i < 8; i++) q[i] = add2(q[i], pA[i]);
    #pragma unroll
    for (int i = 0; i < 8; i++) tot[i] = add2(c01[i], q[i]);
    constexpr int KMAIN = K & ~7;
    #pragma unroll
    for (int k = KMAIN; k < K; k++) {
        ull wp = pack2(__ldg(wj + (size_t)k * Hs));
        const ulonglong2* sp = (const ulonglong2*)(smat + k * 16);
        ulonglong2 v0 = sp[0], v1 = sp[1], v2 = sp[2], v3 = sp[3];
        fma2(tot[0], v0.x, wp); fma2(tot[1], v0.y, wp);
        fma2(tot[2], v1.x, wp); fma2(tot[3], v1.y, wp);
        fma2(tot[4], v2.x, wp); fma2(tot[5], v2.y, wp);
        fma2(tot[6], v3.x, wp); fma2(tot[7], v3.y, wp);
    }
}

// ================= split GEMM1 pass (FIN=192): xi prefix hoisted per point =================
// Per class l: chain k=l,l+8,...,184 over xi (per-POINT, shared by its 4 edges),
// then continue k=192+l,... over dx (per-edge). Identical op sequence to R12.
template<int L>
__device__ __forceinline__ void pass_split(ull pA[8], ull pB[8],
                                           const float* __restrict__ wj, int Hs,
                                           const float* __restrict__ sxi,
                                           const float* __restrict__ sdx) {
    // lo chains: 4 points (2 ull per class)
    ull a01 = 0, a23 = 0, b01 = 0, b23 = 0;
    #pragma unroll 4
    for (int kc = 0; kc < 192; kc += 8) {
        float wa = __ldg(wj + (size_t)(kc + L) * Hs);
        float wb = __ldg(wj + (size_t)(kc + L + 4) * Hs);
        ull wpa = pack2(wa), wpb = pack2(wb);
        const ull* xa = (const ull*)(sxi + (kc + L) * 4);
        fma2(a01, xa[0], wpa); fma2(a23, xa[1], wpa);
        const ull* xb = (const ull*)(sxi + (kc + L + 4) * 4);
        fma2(b01, xb[0], wpb); fma2(b23, xb[1], wpb);
    }
    // expand point partials to the 16 edge accumulators (edges 4p..4p+3 <- point p)
    {
        float2 v01 = unpack2(a01), v23 = unpack2(a23);
        pA[0] = pack2(v01.x); pA[1] = pack2(v01.x);
        pA[2] = pack2(v01.y); pA[3] = pack2(v01.y);
        pA[4] = pack2(v23.x); pA[5] = pack2(v23.x);
        pA[6] = pack2(v23.y); pA[7] = pack2(v23.y);
        float2 u01 = unpack2(b01), u23 = unpack2(b23);
        pB[0] = pack2(u01.x); pB[1] = pack2(u01.x);
        pB[2] = pack2(u01.y); pB[3] = pack2(u01.y);
        pB[4] = pack2(u23.x); pB[5] = pack2(u23.x);
        pB[6] = pack2(u23.y); pB[7] = pack2(u23.y);
    }
    // hi chains: per-edge dx part, orig k = 192 + kd
    const float* wj2 = wj + (size_t)192 * Hs;
    #pragma unroll 2
    for (int kc = 0; kc < 192; kc += 8) {
        float wa = __ldg(wj2 + (size_t)(kc + L) * Hs);
        float wb = __ldg(wj2 + (size_t)(kc + L + 4) * Hs);
        ull wpa = pack2(wa), wpb = pack2(wb);
        const ulonglong2* sa = (const ulonglong2*)(sdx + (kc + L) * 16);
        ulonglong2 a0 = sa[0], a1 = sa[1], a2 = sa[2], a3 = sa[3];
        fma2(pA[0], a0.x, wpa); fma2(pA[1], a0.y, wpa);
        fma2(pA[2], a1.x, wpa); fma2(pA[3], a1.y, wpa);
        fma2(pA[4], a2.x, wpa); fma2(pA[5], a2.y, wpa);
        fma2(pA[6], a3.x, wpa); fma2(pA[7], a3.y, wpa);
        const ulonglong2* sb = (const ulonglong2*)(sdx + (kc + L + 4) * 16);
        ulonglong2 b0 = sb[0], b1 = sb[1], b2 = sb[2], b3 = sb[3];
        fma2(pB[0], b0.x, wpb); fma2(pB[1], b0.y, wpb);
        fma2(pB[2], b1.x, wpb); fma2(pB[3], b1.y, wpb);
        fma2(pB[4], b2.x, wpb); fma2(pB[5], b2.y, wpb);
        fma2(pB[6], b3.x, wpb); fma2(pB[7], b3.y, wpb);
    }
}
__device__ __forceinline__ void gemm1_split(ull tot[8],
                                            const float* __restrict__ wj, int Hs,
                                            const float* __restrict__ sxi,
                                            const float* __restrict__ sdx) {
    ull c01[8], q[8], pA[8], pB[8];
    pass_split<0>(pA, pB, wj, Hs, sxi, sdx);
    #pragma unroll
    for (int i = 0; i < 8; i++) c01[i] = add2(pA[i], pB[i]);
    pass_split<1>(pA, pB, wj, Hs, sxi, sdx);
    #pragma unroll
    for (int i = 0; i < 8; i++) q[i] = add2(pA[i], pB[i]);
    #pragma unroll
    for (int i = 0; i < 8; i++) c01[i] = add2(c01[i], q[i]);
    pass_split<2>(pA, pB, wj, Hs, sxi, sdx);
    #pragma unroll
    for (int i = 0; i < 8; i++) q[i] = add2(pA[i], pB[i]);
    pass_split<3>(pA, pB, wj, Hs, sxi, sdx);
    #pragma unroll
    for (int i = 0; i < 8; i++) pA[i] = add2(pA[i], pB[i]);
    #pragma unroll
    for (int i = 0; i < 8; i++) q[i] = add2(q[i], pA[i]);
    #pragma unroll
    for (int i = 0; i < 8; i++) tot[i] = add2(c01[i], q[i]);
    // K=384: no tail
}

// ---------------- conv1 EdgeConv (FIN=4): R12 generic path ----------------
__global__ void __launch_bounds__(256, 2)
edgeconv1_kernel(const float* __restrict__ feat,
                 const int* __restrict__ idx,
                 const float* __restrict__ w1, const float* __restrict__ b1,
                 const float* __restrict__ w2, const float* __restrict__ b2,
                 float* __restrict__ out) {
    constexpr int FIN = 4, H = 96, Cout = 192, F2 = 8;
    __shared__ __align__(16) float sf[F2 * 16];
    __shared__ __align__(16) float s[H * 16];
    __shared__ int nb[16];
    int m0 = blockIdx.x * 4;
    int tid = threadIdx.x;
    if (tid < 16) {
        int p = tid >> 2;
        int m = m0 + p;
        nb[tid] = (m & ~(NN - 1)) + idx[m * KNNK + (tid & 3)];
    }
    __syncthreads();
    if (tid < F2 * 16) {
        int e = tid & 15, k = tid >> 4;
        int p = e >> 2;
        float v;
        if (k < FIN) v = feat[(size_t)(m0 + p) * FIN + k];
        else {
            int kk = k - FIN;
            v = __fadd_rn(feat[(size_t)nb[e] * FIN + kk], -feat[(size_t)(m0 + p) * FIN + kk]);
        }
        sf[tid] = v;
    }
    __syncthreads();
    if (tid < H) {
        int j = tid;
        ull tot[8];
        gemm_col16<F2>(tot, w1 + j, H, sf);
        float bb = b1[j];
        #pragma unroll
        for (int u = 0; u < 4; u++) {
            float2 r0 = unpack2(tot[2 * u]);
            float2 r1 = unpack2(tot[2 * u + 1]);
            *(float4*)(s + j * 16 + 4 * u) =
                make_float4(leakyf(__fadd_rn(r0.x, bb)), leakyf(__fadd_rn(r0.y, bb)),
                            leakyf(__fadd_rn(r1.x, bb)), leakyf(__fadd_rn(r1.y, bb)));
        }
    }
    __syncthreads();
    if (tid < Cout) {
        int o = tid;
        ull tot[8];
        gemm_col16<H>(tot, w2 + o, Cout, s);
        float bb = b2[o];
        #pragma unroll
        for (int p = 0; p < 4; p++) {
            float2 x0 = unpack2(tot[2 * p]);
            float2 x1 = unpack2(tot[2 * p + 1]);
            float r = leakyf(x0.x + bb) + leakyf(x0.y + bb) +
                      leakyf(x1.x + bb) + leakyf(x1.y + bb);
            out[(size_t)(m0 + p) * Cout + o] = r;
        }
    }
}

// ---------------- heavy EdgeConv (FIN=192, H=252): split GEMM1 ----------------
__global__ void __launch_bounds__(256, 2)
edgeconv_split_kernel(const float* __restrict__ feat,
                      const int* __restrict__ idx,
                      const float* __restrict__ w1, const float* __restrict__ b1,
                      const float* __restrict__ w2, const float* __restrict__ b2,
                      float* __restrict__ out) {
    constexpr int FIN = 192, H = 252, Cout = 192;
    __shared__ __align__(16) float sxi[FIN * 4];    // [k*4 + p]
    __shared__ __align__(16) float sdx[FIN * 16];   // [k*16 + e]
    __shared__ __align__(16) float s[H * 16];       // [j*16 + e]
    __shared__ int nb[16];

    int m0 = blockIdx.x * 4;
    int tid = threadIdx.x;

    if (tid < 16) {
        int p = tid >> 2;
        int m = m0 + p;
        nb[tid] = (m & ~(NN - 1)) + idx[m * KNNK + (tid & 3)];
    }
    __syncthreads();

    for (int t = tid; t < FIN * 4; t += 256) {
        int p = t & 3, k = t >> 2;
        sxi[t] = feat[(size_t)(m0 + p) * FIN + k];
    }
    #pragma unroll 2
    for (int t = tid; t < FIN * 16; t += 256) {
        int e = t & 15, k = t >> 4;
        int p = e >> 2;
        sdx[t] = __fadd_rn(feat[(size_t)nb[e] * FIN + k], -feat[(size_t)(m0 + p) * FIN + k]);
    }
    __syncthreads();

    // GEMM 1 (split): s = leaky(e @ w1 + b1)
    if (tid < H) {
        int j = tid;
        ull tot[8];
        gemm1_split(tot, w1 + j, H, sxi, sdx);
        float bb = b1[j];
        #pragma unroll
        for (int u = 0; u < 4; u++) {
            float2 r0 = unpack2(tot[2 * u]);
            float2 r1 = unpack2(tot[2 * u + 1]);
            *(float4*)(s + j * 16 + 4 * u) =
                make_float4(leakyf(__fadd_rn(r0.x, bb)), leakyf(__fadd_rn(r0.y, bb)),
                            leakyf(__fadd_rn(r1.x, bb)), leakyf(__fadd_rn(r1.y, bb)));
        }
    }
    __syncthreads();

    // GEMM 2 (generic class-pair over H=252)
    if (tid < Cout) {
        int o = tid;
        ull tot[8];
        gemm_col16<H>(tot, w2 + o, Cout, s);
        float bb = b2[o];
        #pragma unroll
        for (int p = 0; p < 4; p++) {
            float2 x0 = unpack2(tot[2 * p]);
            float2 x1 = unpack2(tot[2 * p + 1]);
            float r = leakyf(x0.x + bb) + leakyf(x0.y + bb) +
                      leakyf(x1.x + bb) + leakyf(x1.y + bb);
            out[(size_t)(m0 + p) * Cout + o] = r;
        }
    }
}

// ---------------- nn1+nn2 fused: 16 points/block, 256 threads, dynamic smem ----------------
// Per-(point,channel) chains sequential ascending k — identical to R7-R12.
__global__ void __launch_bounds__(256)
nn12_kernel(const float* __restrict__ x,
            const float* __restrict__ a, const float* __restrict__ b,
            const float* __restrict__ c, const float* __restrict__ d,
            const float* __restrict__ w1, const float* __restrict__ b1,
            const float* __restrict__ w2, const float* __restrict__ b2,
            float* __restrict__ hout) {
    extern __shared__ float dyn_[];
    float* sin_ = dyn_;               // [ch*16 + p], 772*16
    float* sh1  = dyn_ + 772 * 16;    // [j*16 + p], 252*16
    int m0 = blockIdx.x * 16;
    int tid = threadIdx.x;
    #pragma unroll 4
    for (int e = tid; e < 772 * 16; e += 256) {
        int ch = e >> 4, p = e & 15;
        size_t mp = (size_t)(m0 + p);
        float val;
        if (ch < 4)        val = x[mp * 4 + ch];
        else if (ch < 196) val = a[mp * 192 + (ch - 4)];
        else if (ch < 388) val = b[mp * 192 + (ch - 196)];
        else if (ch < 580) val = c[mp * 192 + (ch - 388)];
        else               val = d[mp * 192 + (ch - 580)];
        sin_[e] = val;
    }
    __syncthreads();
    if (tid < 252) {
        int j = tid;
        ull acc[8];
        #pragma unroll
        for (int i = 0; i < 8; i++) acc[i] = 0;
        #pragma unroll 2
        for (int k = 0; k < 772; k++) {
            ull wp = pack2(__ldg(w1 + (size_t)k * 252 + j));
            const ulonglong2* sp = (const ulonglong2*)(sin_ + k * 16);
            ulonglong2 s0 = sp[0], s1 = sp[1], s2 = sp[2], s3 = sp[3];
            fma2(acc[0], s0.x, wp); fma2(acc[1], s0.y, wp);
            fma2(acc[2], s1.x, wp); fma2(acc[3], s1.y, wp);
            fma2(acc[4], s2.x, wp); fma2(acc[5], s2.y, wp);
            fma2(acc[6], s3.x, wp); fma2(acc[7], s3.y, wp);
        }
        float bb = b1[j];
        #pragma unroll
        for (int u = 0; u < 4; u++) {
            float2 r0 = unpack2(acc[2 * u]);
            float2 r1 = unpack2(acc[2 * u + 1]);
            *(float4*)(sh1 + j * 16 + 4 * u) =
                make_float4(leakyf(r0.x + bb), leakyf(r0.y + bb),
                            leakyf(r1.x + bb), leakyf(r1.y + bb));
        }
    }
    __syncthreads();
    if (tid < 192) {
        int o = tid;
        ull acc[8];
        #pragma unroll
        for (int i = 0; i < 8; i++) acc[i] = 0;
        #pragma unroll 2
        for (int mm = 0; mm < 252; mm++) {
            ull wp = pack2(__ldg(w2 + mm * 192 + o));
            const ulonglong2* sp = (const ulonglong2*)(sh1 + mm * 16);
            ulonglong2 s0 = sp[0], s1 = sp[1], s2 = sp[2], s3 = sp[3];
            fma2(acc[0], s0.x, wp); fma2(acc[1], s0.y, wp);
            fma2(acc[2], s1.x, wp); fma2(acc[3], s1.y, wp);
            fma2(acc[4], s2.x, wp); fma2(acc[5], s2.y, wp);
            fma2(acc[6], s3.x, wp); fma2(acc[7], s3.y, wp);
        }
        float bb = b2[o];
        #pragma unroll
        for (int u = 0; u < 8; u++) {
            float2 r = unpack2(acc[u]);
            hout[(size_t)(m0 + 2 * u) * 192 + o]     = r.x + bb;
            hout[(size_t)(m0 + 2 * u + 1) * 192 + o] = r.y + bb;
        }
    }
}

// ---------------- pooling (unchanged) ----------------
__global__ void pool_kernel(const float* __restrict__ h, float* __restrict__ pooled) {
    int b = blockIdx.x, cch = threadIdx.x;
    const float* hp = h + (size_t)b * NN * 192 + cch;
    float mx = -1e38f, mn = 1e38f;
    double sm = 0.0;
    #pragma unroll 4
    for (int n = 0; n < NN; n++) {
        float v = hp[(size_t)n * 192];
        mx = fmaxf(mx, v); mn = fminf(mn, v);
        sm += (double)v;
    }
    float smf = (float)sm;
    float* pb = pooled + b * 768;
    pb[cch]       = leakyf(mx);
    pb[192 + cch] = leakyf(mn);
    pb[384 + cch] = leakyf(smf);
    pb[576 + cch] = leakyf(__fmul_rn(smf, (1.0f / 256.0f)));
}

// ---------------- final head (unchanged) ----------------
__global__ void final_kernel(const float* __restrict__ pooled,
                             const float* __restrict__ w3, const float* __restrict__ b3,
                             const float* __restrict__ w4, const float* __restrict__ b4,
                             float* __restrict__ out) {
    __shared__ float sp[768];
    __shared__ float smid[96];
    int b = blockIdx.x, tid = threadIdx.x;
    for (int e = tid; e < 768; e += blockDim.x) sp[e] = pooled[b * 768 + e];
    __syncthreads();
    if (tid < 96) {
        float acc = 0.f;
        for (int k = 0; k < 768; k++) acc = fmaf(sp[k], w3[k * 96 + tid], acc);
        smid[tid] = leakyf(acc + b3[tid]);
    }
    __syncthreads();
    if (tid == 0) {
        float sacc = 0.f;
        for (int k = 0; k < 96; k++) sacc = fmaf(smid[k], w4[k], sacc);
        out[b] = sacc + b4[0];
    }
}

// ---------------- launch ----------------
extern "C" void kernel_launch(void* const* d_in, const int* in_sizes, int n_in,
                              void* d_out, int out_size) {
    const float* x = (const float*)d_in[0];
    const float* prm[24];
    for (int i = 0; i < 24; i++) prm[i] = (const float*)d_in[i + 1];

    float *ga, *gb, *gc, *gd, *gh, *gp;
    int* gi;
    cudaGetSymbolAddress((void**)&ga, g_a);
    cudaGetSymbolAddress((void**)&gb, g_b);
    cudaGetSymbolAddress((void**)&gc, g_c);
    cudaGetSymbolAddress((void**)&gd, g_d);
    cudaGetSymbolAddress((void**)&gh, g_h);
    cudaGetSymbolAddress((void**)&gp, g_pool);
    cudaGetSymbolAddress((void**)&gi, g_idx);

    int nn12_smem = (772 + 252) * 16 * 4;   // 65536 B
    cudaFuncSetAttribute(nn12_kernel, cudaFuncAttributeMaxDynamicSharedMemorySize, nn12_smem);

    knn_kernel<<<BB, NN>>>(x, 4, gi);
    edgeconv1_kernel<<<NPTS / 4, 256>>>(x, gi, prm[0], prm[1], prm[2], prm[3], ga);

    knn_kernel<<<BB, NN>>>(ga, 192, gi);
    edgeconv_split_kernel<<<NPTS / 4, 256>>>(ga, gi, prm[4], prm[5], prm[6], prm[7], gb);

    knn_kernel<<<BB, NN>>>(gb, 192, gi);
    edgeconv_split_kernel<<<NPTS / 4, 256>>>(gb, gi, prm[8], prm[9], prm[10], prm[11], gc);

    knn_kernel<<<BB, NN>>>(gc, 192, gi);
    edgeconv_split_kernel<<<NPTS / 4, 256>>>(gc, gi, prm[12], prm[13], prm[14], prm[15], gd);

    nn12_kernel<<<NPTS / 16, 256, nn12_smem>>>(x, ga, gb, gc, gd,
                                               prm[16], prm[17], prm[18], prm[19], gh);

    pool_kernel<<<BB, 192>>>(gh, gp);
    final_kernel<<<BB, 128>>>(gp, prm[20], prm[21], prm[22], prm[23], (float*)d_out);
}